// round 8
// baseline (speedup 1.0000x reference)
#include <cuda_runtime.h>
#include <cuda_fp16.h>

// Problem constants (fixed by the reference):
// B=4, N=8, H=512, W=512, C=65536, SCALING=10, EPS=1e-10, ITERS=17
// attrs layout: [bbox(4), area(1), angle(1), pca_big(1), pca_small(1), hu(7)] = 15 cols
#define NB 4
#define NN 8
#define NC 65536
#define NATTR 15
#define TOT (NB * NN * NC)        // 2,097,152 elements
#define NPIX (NB * NN * 512 * 512)
#define EPSF 1e-10f
#define CK 8192                   // smem chunk size -> 8 chunks per row, 64 KB smem
#define CT 512                    // resolve kernel threads (3 CTAs/SM resident)
#define NCHUNK (TOT / CK)         // 256 chunks total; all resident at once
#define GSLICE 4                  // gather slices per row -> 128 blocks, 1 wave

// Packed state: low 32b = float s (partial ancestor sum), high 32b = int p.
__device__ unsigned long long g_sp[TOT];            // 16 MB (score -> resolve)
__device__ float g_valf[TOT];                       // 8 MB final sums (f32, for cascade)
__device__ __align__(16) __half g_val[TOT];         // 4 MB final values (*0.1, fp16)
__device__ unsigned int g_flag[NCHUNK];             // chunk publish flags

__device__ __forceinline__ unsigned long long pack_sp(float s, int p) {
    return (unsigned long long)(unsigned int)__float_as_int(s)
         | ((unsigned long long)(unsigned int)p << 32);
}
__device__ __forceinline__ float sp_s(unsigned long long v) {
    return __int_as_float((int)(unsigned int)v);
}
__device__ __forceinline__ int sp_p(unsigned long long v) {
    return (int)(v >> 32);
}

// ---------------------------------------------------------------------------
// Phase 1: w = diff * sigmoid(_log_scaling(attrs) . weight[n] + bias[n]);
// init packed state {w, parent}. Also zeroes the chunk publish flags (stream
// order guarantees this precedes the resolve kernel on every graph replay).
// ---------------------------------------------------------------------------
__global__ void __launch_bounds__(256) score_kernel(
    const float* __restrict__ diff, const float* __restrict__ attrs,
    const float* __restrict__ weight, const float* __restrict__ bias,
    const int* __restrict__ parent)
{
    __shared__ float sa[256 * NATTR];
    const int base = blockIdx.x * 256;
    if (threadIdx.x == 0 && blockIdx.x < NCHUNK) g_flag[blockIdx.x] = 0u;

    const float4* ap = (const float4*)(attrs + (size_t)base * NATTR);
    #pragma unroll
    for (int k = threadIdx.x; k < 256 * NATTR / 4; k += 256)
        ((float4*)sa)[k] = ap[k];
    __syncthreads();

    const int idx = base + threadIdx.x;
    const float* f = &sa[threadIdx.x * NATTR];
    const int n = (idx >> 16) & (NN - 1);      // all 256 elems share one n
    const float* wg = weight + n * 17;

    // feats: [bbox0..3, log(area), signed-log f[6..14] (9), lshape, cos, sin]
    float logit = bias[n];
    logit += f[0] * wg[0] + f[1] * wg[1] + f[2] * wg[2] + f[3] * wg[3];
    logit += logf(f[4]) * wg[4];
    #pragma unroll
    for (int k = 0; k < 9; k++) {
        float x = f[6 + k];
        float sg = (float)((x > 0.0f) - (x < 0.0f));
        logit += sg * logf(fabsf(x) + EPSF) * wg[5 + k];
    }
    logit += (sqrtf(f[7]) / (sqrtf(f[6]) + EPSF)) * wg[14];
    float sn, cs;
    sincosf(f[5], &sn, &cs);
    logit += cs * wg[15] + sn * wg[16];

    const float score = 1.0f / (1.0f + expf(-logit));
    g_sp[idx] = pack_sp(diff[idx] * score, parent[idx]);
}

// ---------------------------------------------------------------------------
// Phase 2 (fused chunk + extract): local smem compression, then chunk-DAG
// pipelined resolution.
//  - Local doubling (racy-but-untorn 8B smem ops) until every pointer
//    escapes the chunk; parent[i] < i guarantees termination.
//  - Escaped pointers target strictly lower chunks of the SAME row. Chunk
//    c-1's publish flag implies (inductively) all chunks < c are published
//    as FINAL sums in g_valf, so ONE gather completes each element.
//  - Publish own finals (f32 + fp16*0.1), fence, set flag.
// All 256 blocks are co-resident (64 KB smem, 3 CTAs/SM); dependencies point
// only to lower blockIdx -> no deadlock.
// ---------------------------------------------------------------------------
__global__ void __launch_bounds__(CT) resolve_kernel() {
    extern __shared__ unsigned long long sp[];
    const int gbase = blockIdx.x * CK;
    const int cbase = gbase & (NC - 1);        // row-local chunk base
    const int clim  = cbase + CK;
    const int rowbase = gbase & ~(NC - 1);

    for (int j = threadIdx.x; j < CK / 2; j += CT)
        ((ulonglong2*)sp)[j] = ((const ulonglong2*)&g_sp[gbase])[j];
    __syncthreads();

    // local pointer doubling
    for (;;) {
        int changed = 0;
        #pragma unroll
        for (int j = 0; j < CK / CT; j++) {
            const int e = threadIdx.x + j * CT;
            unsigned long long v = sp[e];
            int p = sp_p(v);
            if (p >= cbase && p < clim) {       // still in-chunk (excludes NC)
                unsigned long long q = sp[p - cbase];
                sp[e] = pack_sp(sp_s(v) + sp_s(q), sp_p(q));
                changed = 1;
            }
        }
        if (!__syncthreads_or(changed)) break;
    }

    // wait for predecessor chunk (same row) to publish its finals
    if (cbase != 0) {
        if (threadIdx.x == 0) {
            while (atomicAdd(&g_flag[blockIdx.x - 1], 0u) == 0u) __nanosleep(64);
        }
        __syncthreads();
        __threadfence();
    }

    // resolve (single gather per escaped element) + publish finals
    #pragma unroll
    for (int j = 0; j < CK / (CT * 2); j++) {
        const int e = (threadIdx.x + j * CT) * 2;
        unsigned long long v0 = sp[e], v1 = sp[e + 1];
        float s0 = sp_s(v0), s1 = sp_s(v1);
        int   p0 = sp_p(v0), p1 = sp_p(v1);
        if (p0 != NC) s0 += __ldcg(&g_valf[rowbase + p0]);
        if (p1 != NC) s1 += __ldcg(&g_valf[rowbase + p1]);
        *(float2*)&g_valf[gbase + e] = make_float2(s0, s1);
        __half2 h = __floats2half2_rn(s0 * 0.1f, s1 * 0.1f);
        *(__half2*)&g_val[gbase + e] = h;
    }

    __threadfence();
    __syncthreads();
    if (threadIdx.x == 0) atomicExch(&g_flag[blockIdx.x], 1u);
}

// ---------------------------------------------------------------------------
// Phase 3: smem-windowed gather. One block per (row, slice); the full
// 65536-entry fp16 value window (128 KB) staged in dynamic smem, pixel
// gathers become LDS. 128 blocks = one full wave; 1024 threads (32 warps/SM).
// ---------------------------------------------------------------------------
__global__ void __launch_bounds__(1024) gather_kernel(
    const int* __restrict__ pix2cc, float* __restrict__ out)
{
    extern __shared__ __half sv[];
    const int row = blockIdx.x >> 2;                 // GSLICE = 4
    const int pbase = blockIdx.x << 16;              // 65536 pixels per block

    const uint4* vals = (const uint4*)(g_val + (row << 16));
    #pragma unroll
    for (int i = threadIdx.x; i < NC * 2 / 16; i += 1024)
        ((uint4*)sv)[i] = __ldcg(&vals[i]);
    __syncthreads();

    const int4* pc = (const int4*)(pix2cc + pbase);
    float4* op = (float4*)(out + pbase);
    #pragma unroll
    for (int i = threadIdx.x; i < 65536 / 4; i += 1024) {
        const int4 cc = __ldg(&pc[i]);
        float4 o;
        o.x = __half2float(sv[cc.x]);
        o.y = __half2float(sv[cc.y]);
        o.z = __half2float(sv[cc.z]);
        o.w = __half2float(sv[cc.w]);
        op[i] = o;
    }
}

// ---------------------------------------------------------------------------
extern "C" void kernel_launch(void* const* d_in, const int* in_sizes, int n_in,
                              void* d_out, int out_size) {
    const float* diff   = (const float*)d_in[0];
    const float* attrs  = (const float*)d_in[1];
    const float* weight = (const float*)d_in[2];
    const float* bias   = (const float*)d_in[3];
    const int*   parent = (const int*)d_in[4];
    const int*   pix2cc = (const int*)d_in[5];
    float* out = (float*)d_out;

    const int chunk_smem  = CK * 8;       // 64 KB
    const int gather_smem = NC * 2;       // 128 KB
    cudaFuncSetAttribute(resolve_kernel,
                         cudaFuncAttributeMaxDynamicSharedMemorySize, chunk_smem);
    cudaFuncSetAttribute(gather_kernel,
                         cudaFuncAttributeMaxDynamicSharedMemorySize, gather_smem);

    score_kernel<<<TOT / 256, 256>>>(diff, attrs, weight, bias, parent);
    resolve_kernel<<<NCHUNK, CT, chunk_smem>>>();
    gather_kernel<<<NB * NN * GSLICE, 1024, gather_smem>>>(pix2cc, out);
}

// round 9
// speedup vs baseline: 1.7153x; 1.7153x over previous
#include <cuda_runtime.h>
#include <cuda_fp16.h>

// Problem constants (fixed by the reference):
// B=4, N=8, H=512, W=512, C=65536, SCALING=10, EPS=1e-10, ITERS=17
// attrs layout: [bbox(4), area(1), angle(1), pca_big(1), pca_small(1), hu(7)] = 15 cols
#define NB 4
#define NN 8
#define NC 65536
#define NATTR 15
#define TOT (NB * NN * NC)        // 2,097,152 elements
#define NPIX (NB * NN * 512 * 512)
#define EPSF 1e-10f
#define CK 16384                  // smem chunk size -> 4 chunks per row
#define CT 1024                   // chunk kernel threads
#define GSLICE 8                  // gather slices per row (256 blocks of 512)

// Packed state: low 32b = float s (partial ancestor sum), high 32b = int p.
__device__ unsigned long long g_sp[TOT];            // 16 MB
__device__ __align__(16) __half g_val[TOT];         // 4 MB final values (*0.1, fp16)

__device__ __forceinline__ unsigned long long pack_sp(float s, int p) {
    return (unsigned long long)(unsigned int)__float_as_int(s)
         | ((unsigned long long)(unsigned int)p << 32);
}
__device__ __forceinline__ float sp_s(unsigned long long v) {
    return __int_as_float((int)(unsigned int)v);
}
__device__ __forceinline__ int sp_p(unsigned long long v) {
    return (int)(v >> 32);
}

// ---------------------------------------------------------------------------
// Phase 1: w = diff * sigmoid(_log_scaling(attrs) . weight[n] + bias[n]);
// init packed state {w, parent}. attrs staged to smem via float4.
// Fast transcendental intrinsics: error on the logit is ~2e-6 (weights are
// |w|<=0.01), invisible next to the fp16 output rounding (2e-4).
// ---------------------------------------------------------------------------
__global__ void __launch_bounds__(256) score_kernel(
    const float* __restrict__ diff, const float* __restrict__ attrs,
    const float* __restrict__ weight, const float* __restrict__ bias,
    const int* __restrict__ parent)
{
    __shared__ float sa[256 * NATTR];
    const int base = blockIdx.x * 256;
    const float4* ap = (const float4*)(attrs + (size_t)base * NATTR);
    #pragma unroll
    for (int k = threadIdx.x; k < 256 * NATTR / 4; k += 256)
        ((float4*)sa)[k] = ap[k];
    __syncthreads();

    const int idx = base + threadIdx.x;
    const float* f = &sa[threadIdx.x * NATTR];
    const int n = (idx >> 16) & (NN - 1);      // all 256 elems share one n
    const float* wg = weight + n * 17;

    // feats: [bbox0..3, log(area), signed-log f[6..14] (9), lshape, cos, sin]
    float logit = bias[n];
    logit += f[0] * wg[0] + f[1] * wg[1] + f[2] * wg[2] + f[3] * wg[3];
    logit += __logf(f[4]) * wg[4];
    #pragma unroll
    for (int k = 0; k < 9; k++) {
        float x = f[6 + k];
        float sg = (float)((x > 0.0f) - (x < 0.0f));
        logit += sg * __logf(fabsf(x) + EPSF) * wg[5 + k];
    }
    logit += __fdividef(__fsqrt_rn(f[7]), __fsqrt_rn(f[6]) + EPSF) * wg[14];
    float sn, cs;
    __sincosf(f[5], &sn, &cs);
    logit += cs * wg[15] + sn * wg[16];

    const float score = __fdividef(1.0f, 1.0f + __expf(-logit));
    g_sp[idx] = pack_sp(diff[idx] * score, parent[idx]);
}

// ---------------------------------------------------------------------------
// Phase 2a: in-smem chunk compression, CK=16384 (128 KB dynamic smem).
// Racy-but-untorn 8B smem doubling until every pointer escapes the chunk
// (p < cbase, or p == NC). parent[i] < i guarantees termination.
// Post-condition: pointers target strictly lower chunks; chunk-0 elements
// are fully rooted. With 4 chunks/row, residual depth <= 3.
// ---------------------------------------------------------------------------
__global__ void __launch_bounds__(CT) chunk_kernel() {
    extern __shared__ unsigned long long sp[];
    const int gbase = blockIdx.x * CK;
    const int cbase = gbase & (NC - 1);        // row-local chunk base
    const int clim  = cbase + CK;

    for (int j = threadIdx.x; j < CK / 2; j += CT)
        ((ulonglong2*)sp)[j] = ((const ulonglong2*)&g_sp[gbase])[j];
    __syncthreads();

    for (;;) {
        int changed = 0;
        #pragma unroll
        for (int j = 0; j < CK / CT; j++) {
            const int e = threadIdx.x + j * CT;
            unsigned long long v = sp[e];
            int p = sp_p(v);
            if (p >= cbase && p < clim) {       // still in-chunk (excludes NC)
                unsigned long long q = sp[p - cbase];
                sp[e] = pack_sp(sp_s(v) + sp_s(q), sp_p(q));
                changed = 1;
            }
        }
        if (!__syncthreads_or(changed)) break;
    }

    for (int j = threadIdx.x; j < CK / 2; j += CT)
        ((ulonglong2*)&g_sp[gbase])[j] = ((const ulonglong2*)sp)[j];
}

// ---------------------------------------------------------------------------
// Phase 2b: extract with bounded chain walk (depth <= 3 after chunking).
// 4 lanes per thread for ILP; folds 1/SCALING; writes compacted fp16 values.
// ---------------------------------------------------------------------------
__global__ void __launch_bounds__(256) extract_kernel() {
    const int t = blockIdx.x * 256 + threadIdx.x;
    const int e0 = t * 4;
    const int rowbase = e0 & ~(NC - 1);        // 4 consecutive elems share row
    ulonglong2 a = __ldcg((const ulonglong2*)&g_sp[e0]);
    ulonglong2 b = __ldcg((const ulonglong2*)&g_sp[e0 + 2]);

    float s0 = sp_s(a.x), s1 = sp_s(a.y), s2 = sp_s(b.x), s3 = sp_s(b.y);
    int   p0 = sp_p(a.x), p1 = sp_p(a.y), p2 = sp_p(b.x), p3 = sp_p(b.y);

    #pragma unroll
    for (int it = 0; it < 3; it++) {
        unsigned long long q0 = (p0 != NC) ? __ldcg(&g_sp[rowbase + p0]) : 0ull;
        unsigned long long q1 = (p1 != NC) ? __ldcg(&g_sp[rowbase + p1]) : 0ull;
        unsigned long long q2 = (p2 != NC) ? __ldcg(&g_sp[rowbase + p2]) : 0ull;
        unsigned long long q3 = (p3 != NC) ? __ldcg(&g_sp[rowbase + p3]) : 0ull;
        if (p0 != NC) { s0 += sp_s(q0); p0 = sp_p(q0); }
        if (p1 != NC) { s1 += sp_s(q1); p1 = sp_p(q1); }
        if (p2 != NC) { s2 += sp_s(q2); p2 = sp_p(q2); }
        if (p3 != NC) { s3 += sp_s(q3); p3 = sp_p(q3); }
    }

    __half2 h01 = __floats2half2_rn(s0 * 0.1f, s1 * 0.1f);
    __half2 h23 = __floats2half2_rn(s2 * 0.1f, s3 * 0.1f);
    uint2 o;
    o.x = *(unsigned int*)&h01;
    o.y = *(unsigned int*)&h23;
    ((uint2*)g_val)[t] = o;
}

// ---------------------------------------------------------------------------
// Phase 3: smem-windowed gather (proven ~16us). One block per (row, slice);
// the full 65536-entry fp16 value window (128 KB) staged in dynamic smem,
// pixel gathers become LDS.
// ---------------------------------------------------------------------------
__global__ void __launch_bounds__(512) gather_kernel(
    const int* __restrict__ pix2cc, float* __restrict__ out)
{
    extern __shared__ __half sv[];
    const int row = blockIdx.x >> 3;                 // GSLICE = 8
    const int pbase = blockIdx.x << 15;              // 32768 pixels per block

    const uint4* vals = (const uint4*)(g_val + (row << 16));
    #pragma unroll
    for (int i = threadIdx.x; i < NC * 2 / 16; i += 512)
        ((uint4*)sv)[i] = __ldcg(&vals[i]);
    __syncthreads();

    const int4* pc = (const int4*)(pix2cc + pbase);
    float4* op = (float4*)(out + pbase);
    #pragma unroll
    for (int i = threadIdx.x; i < 32768 / 4; i += 512) {
        const int4 cc = __ldg(&pc[i]);
        float4 o;
        o.x = __half2float(sv[cc.x]);
        o.y = __half2float(sv[cc.y]);
        o.z = __half2float(sv[cc.z]);
        o.w = __half2float(sv[cc.w]);
        op[i] = o;
    }
}

// ---------------------------------------------------------------------------
extern "C" void kernel_launch(void* const* d_in, const int* in_sizes, int n_in,
                              void* d_out, int out_size) {
    const float* diff   = (const float*)d_in[0];
    const float* attrs  = (const float*)d_in[1];
    const float* weight = (const float*)d_in[2];
    const float* bias   = (const float*)d_in[3];
    const int*   parent = (const int*)d_in[4];
    const int*   pix2cc = (const int*)d_in[5];
    float* out = (float*)d_out;

    const int chunk_smem  = CK * 8;       // 128 KB
    const int gather_smem = NC * 2;       // 128 KB
    cudaFuncSetAttribute(chunk_kernel,
                         cudaFuncAttributeMaxDynamicSharedMemorySize, chunk_smem);
    cudaFuncSetAttribute(gather_kernel,
                         cudaFuncAttributeMaxDynamicSharedMemorySize, gather_smem);

    score_kernel<<<TOT / 256, 256>>>(diff, attrs, weight, bias, parent);
    chunk_kernel<<<TOT / CK, CT, chunk_smem>>>();
    extract_kernel<<<TOT / 1024, 256>>>();
    gather_kernel<<<NB * NN * GSLICE, 512, gather_smem>>>(pix2cc, out);
}

// round 10
// speedup vs baseline: 1.7461x; 1.0180x over previous
#include <cuda_runtime.h>
#include <cuda_fp16.h>

// Problem constants (fixed by the reference):
// B=4, N=8, H=512, W=512, C=65536, SCALING=10, EPS=1e-10, ITERS=17
// attrs layout: [bbox(4), area(1), angle(1), pca_big(1), pca_small(1), hu(7)] = 15 cols
#define NB 4
#define NN 8
#define NC 65536
#define NATTR 15
#define TOT (NB * NN * NC)        // 2,097,152 elements
#define NPIX (NB * NN * 512 * 512)
#define EPSF 1e-10f
#define CK 16384                  // smem chunk size -> 4 chunks per row
#define CT 1024                   // chunk kernel threads
#define GSLICE 4                  // gather slices per row -> 128 blocks, 1 wave

// Packed state: low 32b = float s (partial ancestor sum), high 32b = int p.
__device__ unsigned long long g_sp[TOT];            // 16 MB
__device__ __align__(16) __half g_val[TOT];         // 4 MB final values (*0.1, fp16)

__device__ __forceinline__ unsigned long long pack_sp(float s, int p) {
    return (unsigned long long)(unsigned int)__float_as_int(s)
         | ((unsigned long long)(unsigned int)p << 32);
}
__device__ __forceinline__ float sp_s(unsigned long long v) {
    return __int_as_float((int)(unsigned int)v);
}
__device__ __forceinline__ int sp_p(unsigned long long v) {
    return (int)(v >> 32);
}

// ---------------------------------------------------------------------------
// Phase 1: w = diff * sigmoid(_log_scaling(attrs) . weight[n] + bias[n]);
// init packed state {w, parent}. attrs staged to smem via float4.
// Fast transcendental intrinsics: error on the logit is ~2e-6 (weights are
// |w|<=0.01), invisible next to the fp16 output rounding (2e-4).
// ---------------------------------------------------------------------------
__global__ void __launch_bounds__(256) score_kernel(
    const float* __restrict__ diff, const float* __restrict__ attrs,
    const float* __restrict__ weight, const float* __restrict__ bias,
    const int* __restrict__ parent)
{
    __shared__ float sa[256 * NATTR];
    const int base = blockIdx.x * 256;
    const float4* ap = (const float4*)(attrs + (size_t)base * NATTR);
    #pragma unroll
    for (int k = threadIdx.x; k < 256 * NATTR / 4; k += 256)
        ((float4*)sa)[k] = ap[k];
    __syncthreads();

    const int idx = base + threadIdx.x;
    const float* f = &sa[threadIdx.x * NATTR];
    const int n = (idx >> 16) & (NN - 1);      // all 256 elems share one n
    const float* wg = weight + n * 17;

    // feats: [bbox0..3, log(area), signed-log f[6..14] (9), lshape, cos, sin]
    float logit = bias[n];
    logit += f[0] * wg[0] + f[1] * wg[1] + f[2] * wg[2] + f[3] * wg[3];
    logit += __logf(f[4]) * wg[4];
    #pragma unroll
    for (int k = 0; k < 9; k++) {
        float x = f[6 + k];
        float sg = (float)((x > 0.0f) - (x < 0.0f));
        logit += sg * __logf(fabsf(x) + EPSF) * wg[5 + k];
    }
    logit += __fdividef(__fsqrt_rn(f[7]), __fsqrt_rn(f[6]) + EPSF) * wg[14];
    float sn, cs;
    __sincosf(f[5], &sn, &cs);
    logit += cs * wg[15] + sn * wg[16];

    const float score = __fdividef(1.0f, 1.0f + __expf(-logit));
    g_sp[idx] = pack_sp(diff[idx] * score, parent[idx]);
}

// ---------------------------------------------------------------------------
// Phase 2a: in-smem chunk compression, CK=16384 (128 KB dynamic smem).
// Racy-but-untorn 8B smem doubling until every pointer escapes the chunk
// (p < cbase, or p == NC). parent[i] < i guarantees termination.
// Post-condition: pointers target strictly lower chunks; chunk-0 elements
// are fully rooted. With 4 chunks/row, residual depth <= 3.
// ---------------------------------------------------------------------------
__global__ void __launch_bounds__(CT) chunk_kernel() {
    extern __shared__ unsigned long long sp[];
    const int gbase = blockIdx.x * CK;
    const int cbase = gbase & (NC - 1);        // row-local chunk base
    const int clim  = cbase + CK;

    for (int j = threadIdx.x; j < CK / 2; j += CT)
        ((ulonglong2*)sp)[j] = ((const ulonglong2*)&g_sp[gbase])[j];
    __syncthreads();

    for (;;) {
        int changed = 0;
        #pragma unroll
        for (int j = 0; j < CK / CT; j++) {
            const int e = threadIdx.x + j * CT;
            unsigned long long v = sp[e];
            int p = sp_p(v);
            if (p >= cbase && p < clim) {       // still in-chunk (excludes NC)
                unsigned long long q = sp[p - cbase];
                sp[e] = pack_sp(sp_s(v) + sp_s(q), sp_p(q));
                changed = 1;
            }
        }
        if (!__syncthreads_or(changed)) break;
    }

    for (int j = threadIdx.x; j < CK / 2; j += CT)
        ((ulonglong2*)&g_sp[gbase])[j] = ((const ulonglong2*)sp)[j];
}

// ---------------------------------------------------------------------------
// Phase 2b: extract with bounded chain walk (depth <= 3 after chunking).
// 4 lanes per thread for ILP; folds 1/SCALING; writes compacted fp16 values.
// ---------------------------------------------------------------------------
__global__ void __launch_bounds__(256) extract_kernel() {
    const int t = blockIdx.x * 256 + threadIdx.x;
    const int e0 = t * 4;
    const int rowbase = e0 & ~(NC - 1);        // 4 consecutive elems share row
    ulonglong2 a = __ldcg((const ulonglong2*)&g_sp[e0]);
    ulonglong2 b = __ldcg((const ulonglong2*)&g_sp[e0 + 2]);

    float s0 = sp_s(a.x), s1 = sp_s(a.y), s2 = sp_s(b.x), s3 = sp_s(b.y);
    int   p0 = sp_p(a.x), p1 = sp_p(a.y), p2 = sp_p(b.x), p3 = sp_p(b.y);

    #pragma unroll
    for (int it = 0; it < 3; it++) {
        unsigned long long q0 = (p0 != NC) ? __ldcg(&g_sp[rowbase + p0]) : 0ull;
        unsigned long long q1 = (p1 != NC) ? __ldcg(&g_sp[rowbase + p1]) : 0ull;
        unsigned long long q2 = (p2 != NC) ? __ldcg(&g_sp[rowbase + p2]) : 0ull;
        unsigned long long q3 = (p3 != NC) ? __ldcg(&g_sp[rowbase + p3]) : 0ull;
        if (p0 != NC) { s0 += sp_s(q0); p0 = sp_p(q0); }
        if (p1 != NC) { s1 += sp_s(q1); p1 = sp_p(q1); }
        if (p2 != NC) { s2 += sp_s(q2); p2 = sp_p(q2); }
        if (p3 != NC) { s3 += sp_s(q3); p3 = sp_p(q3); }
    }

    __half2 h01 = __floats2half2_rn(s0 * 0.1f, s1 * 0.1f);
    __half2 h23 = __floats2half2_rn(s2 * 0.1f, s3 * 0.1f);
    uint2 o;
    o.x = *(unsigned int*)&h01;
    o.y = *(unsigned int*)&h23;
    ((uint2*)g_val)[t] = o;
}

// ---------------------------------------------------------------------------
// Phase 3: smem-windowed gather. One block per (row, slice); full 65536-entry
// fp16 window (128 KB) in dynamic smem. 1024 threads -> 32 warps/SM for
// latency hiding; 128 blocks = one clean wave; window reload traffic halved.
// ---------------------------------------------------------------------------
__global__ void __launch_bounds__(1024) gather_kernel(
    const int* __restrict__ pix2cc, float* __restrict__ out)
{
    extern __shared__ __half sv[];
    const int row = blockIdx.x >> 2;                 // GSLICE = 4
    const int pbase = blockIdx.x << 16;              // 65536 pixels per block

    const uint4* vals = (const uint4*)(g_val + (row << 16));
    #pragma unroll
    for (int i = threadIdx.x; i < NC * 2 / 16; i += 1024)
        ((uint4*)sv)[i] = __ldcg(&vals[i]);
    __syncthreads();

    const int4* pc = (const int4*)(pix2cc + pbase);
    float4* op = (float4*)(out + pbase);
    #pragma unroll
    for (int i = threadIdx.x; i < 65536 / 4; i += 1024) {
        const int4 cc = __ldg(&pc[i]);
        float4 o;
        o.x = __half2float(sv[cc.x]);
        o.y = __half2float(sv[cc.y]);
        o.z = __half2float(sv[cc.z]);
        o.w = __half2float(sv[cc.w]);
        op[i] = o;
    }
}

// ---------------------------------------------------------------------------
extern "C" void kernel_launch(void* const* d_in, const int* in_sizes, int n_in,
                              void* d_out, int out_size) {
    const float* diff   = (const float*)d_in[0];
    const float* attrs  = (const float*)d_in[1];
    const float* weight = (const float*)d_in[2];
    const float* bias   = (const float*)d_in[3];
    const int*   parent = (const int*)d_in[4];
    const int*   pix2cc = (const int*)d_in[5];
    float* out = (float*)d_out;

    const int chunk_smem  = CK * 8;       // 128 KB
    const int gather_smem = NC * 2;       // 128 KB
    cudaFuncSetAttribute(chunk_kernel,
                         cudaFuncAttributeMaxDynamicSharedMemorySize, chunk_smem);
    cudaFuncSetAttribute(gather_kernel,
                         cudaFuncAttributeMaxDynamicSharedMemorySize, gather_smem);

    score_kernel<<<TOT / 256, 256>>>(diff, attrs, weight, bias, parent);
    chunk_kernel<<<TOT / CK, CT, chunk_smem>>>();
    extract_kernel<<<TOT / 1024, 256>>>();
    gather_kernel<<<NB * NN * GSLICE, 1024, gather_smem>>>(pix2cc, out);
}

// round 11
// speedup vs baseline: 1.8622x; 1.0665x over previous
#include <cuda_runtime.h>
#include <cuda_fp16.h>

// Problem constants (fixed by the reference):
// B=4, N=8, H=512, W=512, C=65536, SCALING=10, EPS=1e-10, ITERS=17
// attrs layout: [bbox(4), area(1), angle(1), pca_big(1), pca_small(1), hu(7)] = 15 cols
#define NB 4
#define NN 8
#define NC 65536
#define NATTR 15
#define TOT (NB * NN * NC)        // 2,097,152 elements
#define NPIX (NB * NN * 512 * 512)
#define EPSF 1e-10f
#define CK 16384                  // smem chunk size -> 4 chunks per row
#define CT 1024                   // chunk kernel threads
#define GSLICE 4                  // gather slices per row -> 128 blocks, 1 wave

// Packed state: low 32b = float s (partial ancestor sum), high 32b = int p.
__device__ unsigned long long g_sp[TOT];            // 16 MB
__device__ __align__(16) __half g_val[TOT];         // 4 MB final values (*0.1, fp16)

__device__ __forceinline__ unsigned long long pack_sp(float s, int p) {
    return (unsigned long long)(unsigned int)__float_as_int(s)
         | ((unsigned long long)(unsigned int)p << 32);
}
__device__ __forceinline__ float sp_s(unsigned long long v) {
    return __int_as_float((int)(unsigned int)v);
}
__device__ __forceinline__ int sp_p(unsigned long long v) {
    return (int)(v >> 32);
}

// ---------------------------------------------------------------------------
// Phase 1: w = diff * sigmoid(_log_scaling(attrs) . weight[n] + bias[n]);
// init packed state {w, parent}. attrs staged to smem via float4.
// Fast transcendental intrinsics: error on the logit is ~2e-6 (weights are
// |w|<=0.01), invisible next to the fp16 output rounding (2e-4).
// ---------------------------------------------------------------------------
__global__ void __launch_bounds__(256) score_kernel(
    const float* __restrict__ diff, const float* __restrict__ attrs,
    const float* __restrict__ weight, const float* __restrict__ bias,
    const int* __restrict__ parent)
{
    __shared__ float sa[256 * NATTR];
    const int base = blockIdx.x * 256;
    const float4* ap = (const float4*)(attrs + (size_t)base * NATTR);
    #pragma unroll
    for (int k = threadIdx.x; k < 256 * NATTR / 4; k += 256)
        ((float4*)sa)[k] = ap[k];
    __syncthreads();

    const int idx = base + threadIdx.x;
    const float* f = &sa[threadIdx.x * NATTR];
    const int n = (idx >> 16) & (NN - 1);      // all 256 elems share one n
    const float* wg = weight + n * 17;

    // feats: [bbox0..3, log(area), signed-log f[6..14] (9), lshape, cos, sin]
    float logit = bias[n];
    logit += f[0] * wg[0] + f[1] * wg[1] + f[2] * wg[2] + f[3] * wg[3];
    logit += __logf(f[4]) * wg[4];
    #pragma unroll
    for (int k = 0; k < 9; k++) {
        float x = f[6 + k];
        float sg = (float)((x > 0.0f) - (x < 0.0f));
        logit += sg * __logf(fabsf(x) + EPSF) * wg[5 + k];
    }
    logit += __fdividef(__fsqrt_rn(f[7]), __fsqrt_rn(f[6]) + EPSF) * wg[14];
    float sn, cs;
    __sincosf(f[5], &sn, &cs);
    logit += cs * wg[15] + sn * wg[16];

    const float score = __fdividef(1.0f, 1.0f + __expf(-logit));
    g_sp[idx] = pack_sp(diff[idx] * score, parent[idx]);
}

// ---------------------------------------------------------------------------
// Phase 2a: in-smem chunk compression via racy path-compressing chain walks.
// Each thread walks its elements' chains through smem (8B untorn reads),
// accumulating s until the pointer escapes the chunk, then stores the
// compressed (s, p_escape). Entries only ever improve (p strictly
// decreases; invariant s = sum over [e, p) preserved), so concurrent racy
// reads are always valid snapshots. Ascending processing order means most
// walks hit already-compressed entries (expected ~1 hop).
// Post-condition: pointers target strictly lower chunks (or NC); with
// 4 chunks/row, residual cross-chunk depth <= 3.
// ---------------------------------------------------------------------------
__global__ void __launch_bounds__(CT) chunk_kernel() {
    extern __shared__ unsigned long long sp[];
    const int gbase = blockIdx.x * CK;
    const int cbase = gbase & (NC - 1);        // row-local chunk base
    const int clim  = cbase + CK;

    for (int j = threadIdx.x; j < CK / 2; j += CT)
        ((ulonglong2*)sp)[j] = ((const ulonglong2*)&g_sp[gbase])[j];
    __syncthreads();

    #pragma unroll
    for (int j = 0; j < CK / CT; j++) {
        const int e = threadIdx.x + j * CT;    // ascending: low elems first
        unsigned long long v = sp[e];
        float s = sp_s(v);
        int   p = sp_p(v);
        while (p >= cbase && p < clim) {       // in-chunk (excludes NC)
            unsigned long long q = sp[p - cbase];
            s += sp_s(q);
            p  = sp_p(q);                      // strictly decreasing
        }
        sp[e] = pack_sp(s, p);                 // publish compressed entry
    }
    __syncthreads();

    for (int j = threadIdx.x; j < CK / 2; j += CT)
        ((ulonglong2*)&g_sp[gbase])[j] = ((const ulonglong2*)sp)[j];
}

// ---------------------------------------------------------------------------
// Phase 2b: extract with bounded chain walk (depth <= 3 after chunking).
// 4 lanes per thread for ILP; folds 1/SCALING; writes compacted fp16 values.
// ---------------------------------------------------------------------------
__global__ void __launch_bounds__(256) extract_kernel() {
    const int t = blockIdx.x * 256 + threadIdx.x;
    const int e0 = t * 4;
    const int rowbase = e0 & ~(NC - 1);        // 4 consecutive elems share row
    ulonglong2 a = __ldcg((const ulonglong2*)&g_sp[e0]);
    ulonglong2 b = __ldcg((const ulonglong2*)&g_sp[e0 + 2]);

    float s0 = sp_s(a.x), s1 = sp_s(a.y), s2 = sp_s(b.x), s3 = sp_s(b.y);
    int   p0 = sp_p(a.x), p1 = sp_p(a.y), p2 = sp_p(b.x), p3 = sp_p(b.y);

    #pragma unroll
    for (int it = 0; it < 3; it++) {
        unsigned long long q0 = (p0 != NC) ? __ldcg(&g_sp[rowbase + p0]) : 0ull;
        unsigned long long q1 = (p1 != NC) ? __ldcg(&g_sp[rowbase + p1]) : 0ull;
        unsigned long long q2 = (p2 != NC) ? __ldcg(&g_sp[rowbase + p2]) : 0ull;
        unsigned long long q3 = (p3 != NC) ? __ldcg(&g_sp[rowbase + p3]) : 0ull;
        if (p0 != NC) { s0 += sp_s(q0); p0 = sp_p(q0); }
        if (p1 != NC) { s1 += sp_s(q1); p1 = sp_p(q1); }
        if (p2 != NC) { s2 += sp_s(q2); p2 = sp_p(q2); }
        if (p3 != NC) { s3 += sp_s(q3); p3 = sp_p(q3); }
    }

    __half2 h01 = __floats2half2_rn(s0 * 0.1f, s1 * 0.1f);
    __half2 h23 = __floats2half2_rn(s2 * 0.1f, s3 * 0.1f);
    uint2 o;
    o.x = *(unsigned int*)&h01;
    o.y = *(unsigned int*)&h23;
    ((uint2*)g_val)[t] = o;
}

// ---------------------------------------------------------------------------
// Phase 3: smem-windowed gather. One block per (row, slice); full 65536-entry
// fp16 window (128 KB) in dynamic smem. 1024 threads (32 warps/SM); 128
// blocks = one clean wave. Streaming hints keep the one-shot pix2cc/out
// traffic from evicting L2-resident state.
// ---------------------------------------------------------------------------
__global__ void __launch_bounds__(1024) gather_kernel(
    const int* __restrict__ pix2cc, float* __restrict__ out)
{
    extern __shared__ __half sv[];
    const int row = blockIdx.x >> 2;                 // GSLICE = 4
    const int pbase = blockIdx.x << 16;              // 65536 pixels per block

    const uint4* vals = (const uint4*)(g_val + (row << 16));
    #pragma unroll
    for (int i = threadIdx.x; i < NC * 2 / 16; i += 1024)
        ((uint4*)sv)[i] = __ldcg(&vals[i]);
    __syncthreads();

    const int4* pc = (const int4*)(pix2cc + pbase);
    float4* op = (float4*)(out + pbase);
    #pragma unroll
    for (int i = threadIdx.x; i < 65536 / 4; i += 1024) {
        const int4 cc = __ldcg(&pc[i]);
        float4 o;
        o.x = __half2float(sv[cc.x]);
        o.y = __half2float(sv[cc.y]);
        o.z = __half2float(sv[cc.z]);
        o.w = __half2float(sv[cc.w]);
        __stcg(&op[i], o);
    }
}

// ---------------------------------------------------------------------------
extern "C" void kernel_launch(void* const* d_in, const int* in_sizes, int n_in,
                              void* d_out, int out_size) {
    const float* diff   = (const float*)d_in[0];
    const float* attrs  = (const float*)d_in[1];
    const float* weight = (const float*)d_in[2];
    const float* bias   = (const float*)d_in[3];
    const int*   parent = (const int*)d_in[4];
    const int*   pix2cc = (const int*)d_in[5];
    float* out = (float*)d_out;

    const int chunk_smem  = CK * 8;       // 128 KB
    const int gather_smem = NC * 2;       // 128 KB
    cudaFuncSetAttribute(chunk_kernel,
                         cudaFuncAttributeMaxDynamicSharedMemorySize, chunk_smem);
    cudaFuncSetAttribute(gather_kernel,
                         cudaFuncAttributeMaxDynamicSharedMemorySize, gather_smem);

    score_kernel<<<TOT / 256, 256>>>(diff, attrs, weight, bias, parent);
    chunk_kernel<<<TOT / CK, CT, chunk_smem>>>();
    extract_kernel<<<TOT / 1024, 256>>>();
    gather_kernel<<<NB * NN * GSLICE, 1024, gather_smem>>>(pix2cc, out);
}